// round 3
// baseline (speedup 1.0000x reference)
#include <cuda_runtime.h>
#include <cuda_bf16.h>
#include <math_constants.h>

// Problem dims (fixed by reference setup_inputs)
#define B    128
#define IN   784
#define H    400
#define OUT  10
#define NC   2                 // hidden neurons per layer1 block
#define NBLK1 (H / NC)         // 200 blocks
#define NW   25                // ceil(784/32) bit words per batch

#define THRESH 0.5f
#define DECAY  0.2f

// Scratch (allocation-free rule: __device__ globals)
__device__ unsigned g_bits[NW * B];        // [word][batch] input spike bitmask
__device__ float    g_spk[B * H];          // h1 spikes as floats
__device__ float    g_pmax[NBLK1 * B];     // per-(block,batch) layer1 max partial
__device__ float    g_pmin[NBLK1 * B];

// ---------------------------------------------------------------------------
// Kernel 0: pack input_vec (B x IN, {0,1} floats) into bit words, transposed
// layout g_bits[w*B + b] for coalesced reads in kernel 1.
// ---------------------------------------------------------------------------
__global__ void k_pack(const float* __restrict__ input_vec) {
    int b = blockIdx.x;
    int lane = threadIdx.x;
    const float* row = input_vec + b * IN;
#pragma unroll
    for (int w = 0; w < NW; ++w) {
        int e = w * 32 + lane;
        float v = (e < IN) ? row[e] : 0.0f;
        unsigned m = __ballot_sync(0xffffffffu, v != 0.0f);
        if (lane == 0) g_bits[w * B + b] = m;
    }
}

// ---------------------------------------------------------------------------
// chunk16 for layer 1: process 16 consecutive events for 2 neurons.
//  - updates running membrane q (sequential, for max/min snapshots)
//  - updates mx/mn
//  - returns the balanced-16 pairwise tree sum of the gated weights
//    (leaf pairing (0,1)(2,3)... then recursive — matches JAX associative_scan)
// ---------------------------------------------------------------------------
__device__ __forceinline__ float2 chunk16_l1(
    unsigned half, const float2* __restrict__ sW, int ebase,
    float2& q, float2& mx, float2& mn)
{
    float sx[16], sy[16];
#pragma unroll
    for (int j = 0; j < 16; ++j) {
        int msk = ((int)(half << (31 - j))) >> 31;   // all-ones if bit j set
        float2 w = sW[ebase + j];
        float tx = __int_as_float(msk & __float_as_int(w.x));
        float ty = __int_as_float(msk & __float_as_int(w.y));
        q.x += tx;  q.y += ty;                        // exact when gated off (t=0)
        mx.x = fmaxf(mx.x, q.x);  mx.y = fmaxf(mx.y, q.y);
        mn.x = fminf(mn.x, q.x);  mn.y = fminf(mn.y, q.y);
        sx[j] = tx; sy[j] = ty;
    }
#pragma unroll
    for (int st = 1; st < 16; st <<= 1)
#pragma unroll
        for (int j = 0; j < 16; j += 2 * st) { sx[j] += sx[j + st]; sy[j] += sy[j + st]; }
    return make_float2(sx[0], sy[0]);
}

// ---------------------------------------------------------------------------
// Kernel 1: layer 1. Block = 2 hidden neurons, thread = one batch.
// Final membrane = mem0 + S, where S is the EXACT JAX associative_scan tree
// sum over the 784 gated weights:
//   S = ((bal256(0:256) + bal256(256:512)) + bal256(512:768)) + bal16(768:784)
// realized as a binary counter over 16-leaf chunks with group folding.
// Max/min snapshots tracked with a running accumulator (tolerance 1e-3 ok).
// ---------------------------------------------------------------------------
__global__ __launch_bounds__(B) void k_layer1(
    const float* __restrict__ W1,       // [H][IN]
    const float* __restrict__ h1_mem0,  // [H]
    float* __restrict__ out_h1mem)      // [B][H] (slice of d_out)
{
    __shared__ float2 sW[IN];           // sW[e] = (w_n0[e], w_n1[e])
    int tid = threadIdx.x;              // batch index
    int n0 = blockIdx.x * NC;

    for (int i = tid; i < NC * IN; i += B) {
        int c = i / IN;
        int e = i - c * IN;
        ((float*)sW)[e * NC + c] = W1[(n0 + c) * IN + e];
    }
    __syncthreads();

    const float2 m = make_float2(h1_mem0[n0 + 0], h1_mem0[n0 + 1]);
    float2 q  = m;                                  // running membrane (snapshots)
    float2 mx = make_float2(-CUDART_INF_F, -CUDART_INF_F);
    float2 mn = make_float2( CUDART_INF_F,  CUDART_INF_F);

    // binary-counter pairwise tree over 48 chunks (3 groups of 16), + chunk 48
    float2 p1, p2, p3, p4, acc;
#pragma unroll 1
    for (int c = 0; c < 48; ++c) {
        unsigned word = g_bits[(c >> 1) * B + tid];
        unsigned half = (c & 1) ? (word >> 16) : (word & 0xffffu);
        float2 s = chunk16_l1(half, sW, c * 16, q, mx, mn);
        if (c & 1) { s.x = p1.x + s.x; s.y = p1.y + s.y;
            if (c & 2) { s.x = p2.x + s.x; s.y = p2.y + s.y;
                if (c & 4) { s.x = p3.x + s.x; s.y = p3.y + s.y;
                    if (c & 8) { s.x = p4.x + s.x; s.y = p4.y + s.y;
                        if (c == 15) acc = s;
                        else { acc.x = acc.x + s.x; acc.y = acc.y + s.y; }
                    } else p4 = s;
                } else p3 = s;
            } else p2 = s;
        } else p1 = s;
    }
    {   // leftover chunk (leaves 768..783) added last (lowest level, high->low cleanup)
        unsigned word = g_bits[24 * B + tid];
        unsigned half = word & 0xffffu;
        float2 s = chunk16_l1(half, sW, 768, q, mx, mn);
        acc.x = acc.x + s.x; acc.y = acc.y + s.y;
    }

    // Final membrane = mem0 + tree-sum (single add, matches reference)
    float f0 = m.x + acc.x;
    float f1 = m.y + acc.y;

    bool sp0 = f0 > THRESH;
    bool sp1 = f1 > THRESH;
    g_spk[tid * H + n0 + 0] = sp0 ? 1.0f : 0.0f;
    g_spk[tid * H + n0 + 1] = sp1 ? 1.0f : 0.0f;
    out_h1mem[tid * H + n0 + 0] = sp0 ? 0.0f : f0 * DECAY;
    out_h1mem[tid * H + n0 + 1] = sp1 ? 0.0f : f1 * DECAY;

    float bmx = fmaxf(mx.x, mx.y);
    float bmn = fminf(mn.x, mn.y);
    g_pmax[blockIdx.x * B + tid] = bmx;
    g_pmin[blockIdx.x * B + tid] = bmn;
}

// ---------------------------------------------------------------------------
// chunk16 for layer 2 (1 neuron): gate = spike float (exactly 0.0/1.0).
// ---------------------------------------------------------------------------
__device__ __forceinline__ float chunk16_l2(
    const float* __restrict__ spk, const float* __restrict__ w2, int ebase,
    float& q, float& mx, float& mn)
{
    float s[16];
#pragma unroll
    for (int j = 0; j < 16; ++j) {
        float t = spk[ebase + j] * w2[ebase + j];   // exact: 0 or w
        q += t;
        mx = fmaxf(mx, q);
        mn = fminf(mn, q);
        s[j] = t;
    }
#pragma unroll
    for (int st = 1; st < 16; st <<= 1)
#pragma unroll
        for (int j = 0; j < 16; j += 2 * st) s[j] += s[j + st];
    return s[0];
}

// ---------------------------------------------------------------------------
// Kernel 2: layer 2 + finalize. Block = one batch, 32 threads.
// Lanes 0..9: one output neuron each. n=400 JAX tree:
//   S = ((bal128(0:128)+bal128(128:256))+bal128(256:384)) + bal16(384:400)
// All lanes fold layer-1 partials; warp-reduce max/min; write outputs.
// ---------------------------------------------------------------------------
__global__ __launch_bounds__(32) void k_layer2(
    const float* __restrict__ W2,       // [OUT][H]
    const float* __restrict__ h2_mem0,  // [OUT]
    float* __restrict__ out_h2s,        // [B][OUT]
    float* __restrict__ out_smax,       // [B]
    float* __restrict__ out_smin,       // [B]
    float* __restrict__ out_h2mem)      // [B][OUT]
{
    __shared__ float spk[H];
    int b = blockIdx.x;
    int lane = threadIdx.x;

    for (int i = lane; i < H; i += 32) spk[i] = g_spk[b * H + i];
    __syncwarp();

    float mx = -CUDART_INF_F;
    float mn =  CUDART_INF_F;
    float fin = 0.0f;

    if (lane < OUT) {
        const float m0 = h2_mem0[lane];
        const float* w2 = W2 + lane * H;
        float q = m0;

        float p1, p2, p3, acc;
#pragma unroll 1
        for (int c = 0; c < 24; ++c) {             // 3 groups of 8 chunks
            float s = chunk16_l2(spk, w2, c * 16, q, mx, mn);
            if (c & 1) { s = p1 + s;
                if (c & 2) { s = p2 + s;
                    if (c & 4) { s = p3 + s;
                        acc = (c == 7) ? s : (acc + s);
                    } else p3 = s;
                } else p2 = s;
            } else p1 = s;
        }
        float s = chunk16_l2(spk, w2, 384, q, mx, mn);  // leftover chunk 24
        acc = acc + s;

        fin = m0 + acc;
    }

    // fold in layer-1 partials
    for (int k = lane; k < NBLK1; k += 32) {
        mx = fmaxf(mx, g_pmax[k * B + b]);
        mn = fminf(mn, g_pmin[k * B + b]);
    }
    // warp reduce
#pragma unroll
    for (int off = 16; off > 0; off >>= 1) {
        mx = fmaxf(mx, __shfl_xor_sync(0xffffffffu, mx, off));
        mn = fminf(mn, __shfl_xor_sync(0xffffffffu, mn, off));
    }

    if (lane < OUT) {
        bool sp = fin > THRESH;
        out_h2s[b * OUT + lane] = sp ? 1.0f : 0.0f;
        out_h2mem[b * OUT + lane] = sp ? 0.0f : fin * DECAY;
    }
    if (lane == 0) {
        out_smax[b] = mx;
        out_smin[b] = mn;
    }
}

// ---------------------------------------------------------------------------
// Launch. Output layout = flat concat of reference return tuple:
//   h2_spiked [B*OUT] | step_max [B] | step_min [B] | h1_mem [B*H] | h2_mem [B*OUT]
// ---------------------------------------------------------------------------
extern "C" void kernel_launch(void* const* d_in, const int* in_sizes, int n_in,
                              void* d_out, int out_size) {
    const float* input_vec = (const float*)d_in[0];
    const float* W1        = (const float*)d_in[1];
    const float* W2        = (const float*)d_in[2];
    const float* h1_mem0   = (const float*)d_in[3];
    const float* h2_mem0   = (const float*)d_in[4];

    float* out = (float*)d_out;
    float* out_h2s   = out;                            // B*OUT
    float* out_smax  = out + B * OUT;                  // B
    float* out_smin  = out + B * OUT + B;              // B
    float* out_h1mem = out + B * OUT + 2 * B;          // B*H
    float* out_h2mem = out + B * OUT + 2 * B + B * H;  // B*OUT

    k_pack<<<B, 32>>>(input_vec);
    k_layer1<<<NBLK1, B>>>(W1, h1_mem0, out_h1mem);
    k_layer2<<<B, 32>>>(W2, h2_mem0, out_h2s, out_smax, out_smin, out_h2mem);
}

// round 4
// speedup vs baseline: 1.6149x; 1.6149x over previous
#include <cuda_runtime.h>
#include <cuda_bf16.h>
#include <math_constants.h>

// Problem dims (fixed by reference setup_inputs)
#define B     128
#define IN    784
#define H     400
#define OUT   10
#define NPAIR 200              // H/2 neuron pairs
#define BG    32               // batches per layer1 block
#define ES    6                // event segments per layer1 block (8 chunks each)
#define NW    25               // ceil(784/32) bit words per batch

#define THRESH 0.5f
#define DECAY  0.2f

// Scratch (allocation-free rule: __device__ globals)
__device__ unsigned g_bits[NW * B];      // [word][batch] input spike bitmask
__device__ float    g_spk[B * H];        // h1 spikes as floats
__device__ float    g_pmax[NPAIR * B];   // per-(pair,batch) layer1 max partial
__device__ float    g_pmin[NPAIR * B];

// ---------------------------------------------------------------------------
// Kernel 0: pack input_vec (B x IN, {0,1} floats) into bit words, transposed
// layout g_bits[w*B + b]. One warp per word: single load + ballot.
// ---------------------------------------------------------------------------
__global__ __launch_bounds__(800) void k_pack(const float* __restrict__ input_vec) {
    int b = blockIdx.x;
    int t = threadIdx.x;
    int w = t >> 5;
    int lane = t & 31;
    int e = t;                       // == w*32 + lane
    float v = (e < IN) ? input_vec[b * IN + e] : 0.0f;
    unsigned m = __ballot_sync(0xffffffffu, v != 0.0f);
    if (lane == 0) g_bits[w * B + b] = m;
}

// ---------------------------------------------------------------------------
// chunk16 for layer 1: 16 consecutive events, 2 neurons.
//  - updates running local prefix q (sequential, for max/min snapshots)
//  - updates mx/mn (every leaf — matches passing R2 kernel's candidate set)
//  - returns the balanced-16 pairwise tree sum of the gated weights
// ---------------------------------------------------------------------------
__device__ __forceinline__ float2 chunk16_l1(
    unsigned half, const float2* __restrict__ sW, int ebase,
    float2& q, float2& mx, float2& mn)
{
    float sx[16], sy[16];
#pragma unroll
    for (int j = 0; j < 16; ++j) {
        int msk = ((int)(half << (31 - j))) >> 31;   // all-ones if bit j set
        float2 w = sW[ebase + j];
        float tx = __int_as_float(msk & __float_as_int(w.x));
        float ty = __int_as_float(msk & __float_as_int(w.y));
        q.x += tx;  q.y += ty;                        // exact when gated off (t=0)
        mx.x = fmaxf(mx.x, q.x);  mx.y = fmaxf(mx.y, q.y);
        mn.x = fminf(mn.x, q.x);  mn.y = fminf(mn.y, q.y);
        sx[j] = tx; sy[j] = ty;
    }
#pragma unroll
    for (int st = 1; st < 16; st <<= 1)
#pragma unroll
        for (int j = 0; j < 16; j += 2 * st) { sx[j] += sx[j + st]; sy[j] += sy[j + st]; }
    return make_float2(sx[0], sy[0]);
}

// ---------------------------------------------------------------------------
// Kernel 1: layer 1. Block = 2 neurons x 32 batches x 6 event segments.
// Segment s handles chunks [8s, 8s+8) (128 events) and builds its bal128 via
// an 8-chunk binary counter; seg 5 additionally does the leftover chunk 48
// (events 768..783), whose tree sum is kept separate but whose snapshots
// continue seg 5's local prefix. Recombination reproduces the exact JAX tree:
//   S = (((t0+t1) + (t2+t3)) + (t4+t5)) + L
// which is identical to the R2-passing ((bal256+bal256)+bal256)+bal16.
// Snapshot max/min recombined with segment-total offsets (approx, tol 1e-3).
// ---------------------------------------------------------------------------
__global__ __launch_bounds__(BG * ES, 5) void k_layer1(
    const float* __restrict__ W1,       // [H][IN]
    const float* __restrict__ h1_mem0,  // [H]
    float* __restrict__ out_h1mem)      // [B][H] (slice of d_out)
{
    __shared__ float2 sW[IN];              // sW[e] = (w_n0[e], w_n1[e])
    __shared__ float2 s_tree[ES][BG];
    __shared__ float2 s_L[BG];
    __shared__ float2 s_px[ES][BG];
    __shared__ float2 s_pn[ES][BG];

    int t   = threadIdx.x;
    int seg = t / BG;                      // 0..5
    int bl  = t % BG;                      // local batch
    int b   = blockIdx.y * BG + bl;        // global batch
    int n0  = blockIdx.x * 2;              // neuron pair base

    // Stage weights: smem[e] = (W1[n0][e], W1[n0+1][e])
    for (int i = t; i < 2 * IN; i += BG * ES) {
        int c = i / IN;
        int e = i - c * IN;
        ((float*)sW)[e * 2 + c] = W1[(n0 + c) * IN + e];
    }
    __syncthreads();

    float2 q  = make_float2(0.0f, 0.0f);   // local weight prefix (from 0)
    float2 mx = make_float2(-CUDART_INF_F, -CUDART_INF_F);
    float2 mn = make_float2( CUDART_INF_F,  CUDART_INF_F);
    float2 p1, p2, p3, tree;

    int c0 = seg * 8;
#pragma unroll 1
    for (int lc = 0; lc < 8; ++lc) {
        int c = c0 + lc;
        unsigned word = g_bits[(c >> 1) * B + b];
        unsigned half = (c & 1) ? (word >> 16) : (word & 0xffffu);
        float2 s = chunk16_l1(half, sW, c * 16, q, mx, mn);
        if (lc & 1) { s.x = p1.x + s.x; s.y = p1.y + s.y;
            if (lc & 2) { s.x = p2.x + s.x; s.y = p2.y + s.y;
                if (lc & 4) { s.x = p3.x + s.x; s.y = p3.y + s.y; tree = s; }
                else p3 = s;
            } else p2 = s;
        } else p1 = s;
    }
    if (seg == ES - 1) {
        // leftover chunk 48 (events 768..783): tree kept separate, snapshots
        // continue seg 5's local prefix.
        unsigned half = g_bits[24 * B + b] & 0xffffu;
        s_L[bl] = chunk16_l1(half, sW, 768, q, mx, mn);
    }
    s_tree[seg][bl] = tree;
    s_px[seg][bl]   = mx;
    s_pn[seg][bl]   = mn;
    __syncthreads();

    if (seg == 0) {                        // 32 finalize threads, one per batch
        float2 m = make_float2(h1_mem0[n0], h1_mem0[n0 + 1]);
        float2 o   = make_float2(0.0f, 0.0f);
        float2 gmx = make_float2(-CUDART_INF_F, -CUDART_INF_F);
        float2 gmn = make_float2( CUDART_INF_F,  CUDART_INF_F);
        float2 g0, g1, g2, prev;
#pragma unroll
        for (int i = 0; i < ES; ++i) {
            float2 tr = s_tree[i][bl];
            float2 px = s_px[i][bl];
            float2 pn = s_pn[i][bl];
            gmx.x = fmaxf(gmx.x, o.x + px.x);  gmx.y = fmaxf(gmx.y, o.y + px.y);
            gmn.x = fminf(gmn.x, o.x + pn.x);  gmn.y = fminf(gmn.y, o.y + pn.y);
            if ((i & 1) == 0) prev = tr;
            else {
                float2 g = make_float2(prev.x + tr.x, prev.y + tr.y);
                if (i == 1) g0 = g; else if (i == 3) g1 = g; else g2 = g;
            }
            o.x += tr.x;  o.y += tr.y;
        }
        float2 L = s_L[bl];
        float Sx = ((g0.x + g1.x) + g2.x) + L.x;
        float Sy = ((g0.y + g1.y) + g2.y) + L.y;
        float f0 = m.x + Sx;
        float f1 = m.y + Sy;

        bool sp0 = f0 > THRESH;
        bool sp1 = f1 > THRESH;
        g_spk[b * H + n0 + 0] = sp0 ? 1.0f : 0.0f;
        g_spk[b * H + n0 + 1] = sp1 ? 1.0f : 0.0f;
        out_h1mem[b * H + n0 + 0] = sp0 ? 0.0f : f0 * DECAY;
        out_h1mem[b * H + n0 + 1] = sp1 ? 0.0f : f1 * DECAY;

        g_pmax[blockIdx.x * B + b] = fmaxf(m.x + gmx.x, m.y + gmx.y);
        g_pmin[blockIdx.x * B + b] = fminf(m.x + gmn.x, m.y + gmn.y);
    }
}

// ---------------------------------------------------------------------------
// chunk16 for layer 2 (1 neuron): gate = spike float (exactly 0.0/1.0).
// ---------------------------------------------------------------------------
__device__ __forceinline__ float chunk16_l2(
    const float* __restrict__ spk, const float* __restrict__ w2, int ebase,
    float& q, float& mx, float& mn)
{
    float s[16];
#pragma unroll
    for (int j = 0; j < 16; ++j) {
        float t = spk[ebase + j] * w2[ebase + j];   // exact: 0 or w
        q += t;
        mx = fmaxf(mx, q);
        mn = fminf(mn, q);
        s[j] = t;
    }
#pragma unroll
    for (int st = 1; st < 16; st <<= 1)
#pragma unroll
        for (int j = 0; j < 16; j += 2 * st) s[j] += s[j + st];
    return s[0];
}

// ---------------------------------------------------------------------------
// Kernel 2: layer 2 + finalize. Block = one batch, 128 threads (4 warps).
// Warps 0..2: one bal128 group each (8 chunks, lanes 0..9 = neurons);
// warp 3: leftover chunk 24 (events 384..399). All 128 threads fold the
// layer-1 partials (max/min are exactly associative). Recombination:
//   S = ((t0 + t1) + t2) + L   — identical to the R2-passing tree for n=400.
// ---------------------------------------------------------------------------
__global__ __launch_bounds__(128) void k_layer2(
    const float* __restrict__ W2,       // [OUT][H]
    const float* __restrict__ h2_mem0,  // [OUT]
    float* __restrict__ out_h2s,        // [B][OUT]
    float* __restrict__ out_smax,       // [B]
    float* __restrict__ out_smin,       // [B]
    float* __restrict__ out_h2mem)      // [B][OUT]
{
    __shared__ float spk[H];
    __shared__ float s_t[4][OUT], s_px[4][OUT], s_pn[4][OUT];
    __shared__ float s_fmx[4], s_fmn[4];
    __shared__ float s_nmx[OUT], s_nmn[OUT];

    int b = blockIdx.x;
    int t = threadIdx.x;
    int w = t >> 5;
    int lane = t & 31;

    for (int i = t; i < H; i += 128) spk[i] = g_spk[b * H + i];

    // layer-1 partial fold (exact; no ordering sensitivity)
    float fmx = -CUDART_INF_F, fmn = CUDART_INF_F;
    for (int k = t; k < NPAIR; k += 128) {
        fmx = fmaxf(fmx, g_pmax[k * B + b]);
        fmn = fminf(fmn, g_pmin[k * B + b]);
    }
#pragma unroll
    for (int off = 16; off > 0; off >>= 1) {
        fmx = fmaxf(fmx, __shfl_xor_sync(0xffffffffu, fmx, off));
        fmn = fminf(fmn, __shfl_xor_sync(0xffffffffu, fmn, off));
    }
    if (lane == 0) { s_fmx[w] = fmx; s_fmn[w] = fmn; }

    __syncthreads();   // spk ready

    if (lane < OUT) {
        const float* w2 = W2 + lane * H;
        float q = 0.0f, px = -CUDART_INF_F, pn = CUDART_INF_F;
        float tr = 0.0f;
        if (w < 3) {
            float pa, pb, pc;
#pragma unroll 1
            for (int lc = 0; lc < 8; ++lc) {
                float s = chunk16_l2(spk, w2, (w * 8 + lc) * 16, q, px, pn);
                if (lc & 1) { s = pa + s;
                    if (lc & 2) { s = pb + s;
                        if (lc & 4) { tr = pc + s; }
                        else pc = s;
                    } else pb = s;
                } else pa = s;
            }
        } else {
            tr = chunk16_l2(spk, w2, 384, q, px, pn);  // leftover chunk 24
        }
        s_t[w][lane]  = tr;
        s_px[w][lane] = px;
        s_pn[w][lane] = pn;
    }
    __syncthreads();

    if (t < OUT) {
        float t0 = s_t[0][t], t1 = s_t[1][t], t2 = s_t[2][t], L = s_t[3][t];
        float m0 = h2_mem0[t];
        float S = ((t0 + t1) + t2) + L;
        float fin = m0 + S;
        float o1 = t0, o2 = t0 + t1, o3 = o2 + t2;
        float mx = fmaxf(fmaxf(s_px[0][t], o1 + s_px[1][t]),
                         fmaxf(o2 + s_px[2][t], o3 + s_px[3][t]));
        float mn = fminf(fminf(s_pn[0][t], o1 + s_pn[1][t]),
                         fminf(o2 + s_pn[2][t], o3 + s_pn[3][t]));
        s_nmx[t] = m0 + mx;
        s_nmn[t] = m0 + mn;
        bool sp = fin > THRESH;
        out_h2s[b * OUT + t]   = sp ? 1.0f : 0.0f;
        out_h2mem[b * OUT + t] = sp ? 0.0f : fin * DECAY;
    }
    __syncthreads();

    if (t == 0) {
        float mx = fmaxf(fmaxf(s_fmx[0], s_fmx[1]), fmaxf(s_fmx[2], s_fmx[3]));
        float mn = fminf(fminf(s_fmn[0], s_fmn[1]), fminf(s_fmn[2], s_fmn[3]));
#pragma unroll
        for (int i = 0; i < OUT; ++i) {
            mx = fmaxf(mx, s_nmx[i]);
            mn = fminf(mn, s_nmn[i]);
        }
        out_smax[b] = mx;
        out_smin[b] = mn;
    }
}

// ---------------------------------------------------------------------------
// Launch. Output layout = flat concat of reference return tuple:
//   h2_spiked [B*OUT] | step_max [B] | step_min [B] | h1_mem [B*H] | h2_mem [B*OUT]
// ---------------------------------------------------------------------------
extern "C" void kernel_launch(void* const* d_in, const int* in_sizes, int n_in,
                              void* d_out, int out_size) {
    const float* input_vec = (const float*)d_in[0];
    const float* W1        = (const float*)d_in[1];
    const float* W2        = (const float*)d_in[2];
    const float* h1_mem0   = (const float*)d_in[3];
    const float* h2_mem0   = (const float*)d_in[4];

    float* out = (float*)d_out;
    float* out_h2s   = out;                            // B*OUT
    float* out_smax  = out + B * OUT;                  // B
    float* out_smin  = out + B * OUT + B;              // B
    float* out_h1mem = out + B * OUT + 2 * B;          // B*H
    float* out_h2mem = out + B * OUT + 2 * B + B * H;  // B*OUT

    k_pack<<<B, 800>>>(input_vec);
    k_layer1<<<dim3(NPAIR, B / BG), BG * ES>>>(W1, h1_mem0, out_h1mem);
    k_layer2<<<B, 128>>>(W2, h2_mem0, out_h2s, out_smax, out_smin, out_h2mem);
}

// round 5
// speedup vs baseline: 1.6190x; 1.0025x over previous
#include <cuda_runtime.h>
#include <cuda_bf16.h>
#include <math_constants.h>

// Problem dims (fixed by reference setup_inputs)
#define B     128
#define IN    784
#define H     400
#define OUT   10
#define NQ    100              // H/4 neuron quads
#define BG    32               // batches per layer1 block
#define ES    6                // event segments (8 chunks = 128 events each)
#define NW    25               // ceil(784/32) bit words per batch

#define THRESH 0.5f
#define DECAY  0.2f

// Scratch (allocation-free rule: __device__ globals)
__device__ unsigned g_bits[NW * B];   // [word][batch] input spike bitmask
__device__ float    g_spk[B * H];     // h1 spikes as floats
__device__ float    g_pmax[NQ * B];   // per-(quad,batch) layer1 max partial
__device__ float    g_pmin[NQ * B];

// ---- packed f32x2 helpers (4 floats in 2x 64-bit regs) ----------------------
struct P4 { unsigned long long a, b; };

__device__ __forceinline__ P4 p4_zero() { P4 r; r.a = 0ull; r.b = 0ull; return r; }

__device__ __forceinline__ P4 p4_pack(float x, float y, float z, float w) {
    P4 r;
    asm("mov.b64 %0, {%2, %3};\n\tmov.b64 %1, {%4, %5};"
        : "=l"(r.a), "=l"(r.b) : "f"(x), "f"(y), "f"(z), "f"(w));
    return r;
}
__device__ __forceinline__ float4 p4_unpack(P4 p) {
    float4 v;
    asm("mov.b64 {%0, %1}, %4;\n\tmov.b64 {%2, %3}, %5;"
        : "=f"(v.x), "=f"(v.y), "=f"(v.z), "=f"(v.w) : "l"(p.a), "l"(p.b));
    return v;
}
__device__ __forceinline__ P4 p4_add(P4 u, P4 v) {
    P4 r;
    asm("add.rn.f32x2 %0, %2, %3;\n\tadd.rn.f32x2 %1, %4, %5;"
        : "=l"(r.a), "=l"(r.b) : "l"(u.a), "l"(v.a), "l"(u.b), "l"(v.b));
    return r;
}

// ---------------------------------------------------------------------------
// Kernel 0: pack input_vec (B x IN, {0,1} floats) into bit words, transposed
// layout g_bits[w*B + b]. One warp per word: single load + ballot.
// ---------------------------------------------------------------------------
__global__ __launch_bounds__(800) void k_pack(const float* __restrict__ input_vec) {
    int b = blockIdx.x;
    int t = threadIdx.x;
    int w = t >> 5;
    int lane = t & 31;
    int e = t;
    float v = (e < IN) ? input_vec[b * IN + e] : 0.0f;
    unsigned m = __ballot_sync(0xffffffffu, v != 0.0f);
    if (lane == 0) g_bits[w * B + b] = m;
}

// ---------------------------------------------------------------------------
// chunk16: 16 consecutive events, 4 neurons. Gating via sign-mask AND
// (bitwise identical to R4-passing kernel). Running packed prefix qp feeds
// per-leaf max/min snapshots. Returns the balanced-16 pairwise tree sum of
// the gated weights via a leaf-level binary counter (same association as the
// array tree: pairs (0,1)(2,3)..., left operand = earlier leaves).
// ---------------------------------------------------------------------------
__device__ __forceinline__ P4 chunk16(
    unsigned half, const float4* __restrict__ sW, int ebase,
    P4& qp, float4& mx, float4& mn)
{
    P4 k1, k2, k4, k8, out;
#pragma unroll
    for (int j = 0; j < 16; ++j) {
        int msk = ((int)(half << (31 - j))) >> 31;   // all-ones if bit j set
        float4 w = sW[ebase + j];
        float tx = __int_as_float(msk & __float_as_int(w.x));
        float ty = __int_as_float(msk & __float_as_int(w.y));
        float tz = __int_as_float(msk & __float_as_int(w.z));
        float tw = __int_as_float(msk & __float_as_int(w.w));
        P4 tp = p4_pack(tx, ty, tz, tw);
        qp = p4_add(qp, tp);                         // exact when gated off
        float4 q = p4_unpack(qp);
        mx.x = fmaxf(mx.x, q.x); mx.y = fmaxf(mx.y, q.y);
        mx.z = fmaxf(mx.z, q.z); mx.w = fmaxf(mx.w, q.w);
        mn.x = fminf(mn.x, q.x); mn.y = fminf(mn.y, q.y);
        mn.z = fminf(mn.z, q.z); mn.w = fminf(mn.w, q.w);
        // leaf-level binary counter (balanced-16 tree, left = earlier)
        if ((j & 1) == 0) {
            k1 = tp;
        } else {
            P4 s = p4_add(k1, tp);
            if ((j & 2) == 0) k2 = s;
            else {
                s = p4_add(k2, s);
                if ((j & 4) == 0) k4 = s;
                else {
                    s = p4_add(k4, s);
                    if (j == 7) k8 = s;
                    else out = p4_add(k8, s);        // j == 15
                }
            }
        }
    }
    return out;
}

// ---------------------------------------------------------------------------
// Kernel 1: layer 1. Block = 4 neurons x 32 batches x 6 event segments
// (192 threads). Segment s handles chunks [8s, 8s+8) (bal128 via 3-level
// chunk counter); seg 5 additionally does leftover chunk 48 (events 768..783)
// with its tree kept separate but snapshots continuing seg 5's local prefix.
// Recombination (identical to R4-passing tree):
//   S = (((t0+t1) + (t2+t3)) + (t4+t5)) + L
// Grid = 100 x 4 = 400 blocks -> single wave at occ>=3.
// ---------------------------------------------------------------------------
__global__ __launch_bounds__(BG * ES, 5) void k_layer1(
    const float* __restrict__ W1,       // [H][IN]
    const float* __restrict__ h1_mem0,  // [H]
    float* __restrict__ out_h1mem)      // [B][H] (slice of d_out)
{
    __shared__ float4 sW[IN];                 // sW[e] = (w_n0..w_n3)[e]
    __shared__ float4 s_tree[ES][BG];
    __shared__ float4 s_px[ES][BG];
    __shared__ float4 s_pn[ES][BG];
    __shared__ float4 s_L[BG];

    int t   = threadIdx.x;
    int seg = t >> 5;                         // 0..5
    int bl  = t & 31;                         // local batch
    int b   = blockIdx.y * BG + bl;           // global batch
    int n0  = blockIdx.x * 4;                 // neuron quad base

    // Stage weights: smem[e] = (W1[n0][e], W1[n0+1][e], W1[n0+2][e], W1[n0+3][e])
    for (int i = t; i < 4 * IN; i += BG * ES) {
        int c = i / IN;
        int e = i - c * IN;
        ((float*)sW)[e * 4 + c] = W1[(n0 + c) * IN + e];
    }
    __syncthreads();

    P4 qp = p4_zero();                        // local weight prefix (from 0)
    float4 mx = make_float4(-CUDART_INF_F, -CUDART_INF_F, -CUDART_INF_F, -CUDART_INF_F);
    float4 mn = make_float4( CUDART_INF_F,  CUDART_INF_F,  CUDART_INF_F,  CUDART_INF_F);
    P4 p1, p2, p3, treeP;

    int c0 = seg * 8;
#pragma unroll 1
    for (int wi = 0; wi < 4; ++wi) {          // 4 words = 8 chunks
        unsigned word = g_bits[((c0 >> 1) + wi) * B + b];
#pragma unroll
        for (int hsel = 0; hsel < 2; ++hsel) {
            int lc = wi * 2 + hsel;
            unsigned half = hsel ? (word >> 16) : (word & 0xffffu);
            P4 s = chunk16(half, sW, (c0 + lc) * 16, qp, mx, mn);
            if (lc & 1) {
                s = p4_add(p1, s);
                if (lc & 2) {
                    s = p4_add(p2, s);
                    if (lc & 4) treeP = p4_add(p3, s);
                    else p3 = s;
                } else p2 = s;
            } else p1 = s;
        }
    }
    if (seg == ES - 1) {
        // leftover chunk 48 (events 768..783): tree separate, snapshots
        // continue seg 5's local prefix.
        unsigned half = g_bits[24 * B + b] & 0xffffu;
        s_L[bl] = p4_unpack(chunk16(half, sW, 768, qp, mx, mn));
    }
    s_tree[seg][bl] = p4_unpack(treeP);
    s_px[seg][bl]   = mx;
    s_pn[seg][bl]   = mn;
    __syncthreads();

    if (seg == 0) {                           // 32 finalize threads, 1/batch
        const float4 m = *(const float4*)(h1_mem0 + n0);
        float4 o   = make_float4(0.f, 0.f, 0.f, 0.f);
        float4 gmx = make_float4(-CUDART_INF_F, -CUDART_INF_F, -CUDART_INF_F, -CUDART_INF_F);
        float4 gmn = make_float4( CUDART_INF_F,  CUDART_INF_F,  CUDART_INF_F,  CUDART_INF_F);
        float4 g0, g1, g2, prev;
#pragma unroll
        for (int i = 0; i < ES; ++i) {
            float4 tr = s_tree[i][bl];
            float4 px = s_px[i][bl];
            float4 pn = s_pn[i][bl];
            gmx.x = fmaxf(gmx.x, o.x + px.x); gmx.y = fmaxf(gmx.y, o.y + px.y);
            gmx.z = fmaxf(gmx.z, o.z + px.z); gmx.w = fmaxf(gmx.w, o.w + px.w);
            gmn.x = fminf(gmn.x, o.x + pn.x); gmn.y = fminf(gmn.y, o.y + pn.y);
            gmn.z = fminf(gmn.z, o.z + pn.z); gmn.w = fminf(gmn.w, o.w + pn.w);
            if ((i & 1) == 0) prev = tr;
            else {
                float4 g = make_float4(prev.x + tr.x, prev.y + tr.y,
                                       prev.z + tr.z, prev.w + tr.w);
                if (i == 1) g0 = g; else if (i == 3) g1 = g; else g2 = g;
            }
            o.x += tr.x; o.y += tr.y; o.z += tr.z; o.w += tr.w;
        }
        float4 L = s_L[bl];
        float4 f;
        f.x = m.x + (((g0.x + g1.x) + g2.x) + L.x);
        f.y = m.y + (((g0.y + g1.y) + g2.y) + L.y);
        f.z = m.z + (((g0.z + g1.z) + g2.z) + L.z);
        f.w = m.w + (((g0.w + g1.w) + g2.w) + L.w);

        float4 spk, hm;
        spk.x = f.x > THRESH ? 1.0f : 0.0f;  hm.x = f.x > THRESH ? 0.0f : f.x * DECAY;
        spk.y = f.y > THRESH ? 1.0f : 0.0f;  hm.y = f.y > THRESH ? 0.0f : f.y * DECAY;
        spk.z = f.z > THRESH ? 1.0f : 0.0f;  hm.z = f.z > THRESH ? 0.0f : f.z * DECAY;
        spk.w = f.w > THRESH ? 1.0f : 0.0f;  hm.w = f.w > THRESH ? 0.0f : f.w * DECAY;
        *(float4*)(g_spk + b * H + n0) = spk;
        *(float4*)(out_h1mem + b * H + n0) = hm;

        g_pmax[blockIdx.x * B + b] =
            fmaxf(fmaxf(m.x + gmx.x, m.y + gmx.y), fmaxf(m.z + gmx.z, m.w + gmx.w));
        g_pmin[blockIdx.x * B + b] =
            fminf(fminf(m.x + gmn.x, m.y + gmn.y), fminf(m.z + gmn.z, m.w + gmn.w));
    }
}

// ---------------------------------------------------------------------------
// chunk16 for layer 2 (1 neuron): gate = spike float (exactly 0.0/1.0).
// ---------------------------------------------------------------------------
__device__ __forceinline__ float chunk16_l2(
    const float* __restrict__ spk, const float* __restrict__ w2, int ebase,
    float& q, float& mx, float& mn)
{
    float s[16];
#pragma unroll
    for (int j = 0; j < 16; ++j) {
        float t = spk[ebase + j] * w2[ebase + j];   // exact: 0 or w
        q += t;
        mx = fmaxf(mx, q);
        mn = fminf(mn, q);
        s[j] = t;
    }
#pragma unroll
    for (int st = 1; st < 16; st <<= 1)
#pragma unroll
        for (int j = 0; j < 16; j += 2 * st) s[j] += s[j + st];
    return s[0];
}

// ---------------------------------------------------------------------------
// Kernel 2: layer 2 + finalize. Block = one batch, 128 threads (4 warps).
// Warps 0..2: one bal128 group each (8 chunks, lanes 0..9 = neurons);
// warp 3: leftover chunk 24 (events 384..399). All 128 threads fold the
// layer-1 partials. Recombination: S = ((t0 + t1) + t2) + L.
// ---------------------------------------------------------------------------
__global__ __launch_bounds__(128) void k_layer2(
    const float* __restrict__ W2,       // [OUT][H]
    const float* __restrict__ h2_mem0,  // [OUT]
    float* __restrict__ out_h2s,        // [B][OUT]
    float* __restrict__ out_smax,       // [B]
    float* __restrict__ out_smin,       // [B]
    float* __restrict__ out_h2mem)      // [B][OUT]
{
    __shared__ float spk[H];
    __shared__ float s_t[4][OUT], s_px[4][OUT], s_pn[4][OUT];
    __shared__ float s_fmx[4], s_fmn[4];
    __shared__ float s_nmx[OUT], s_nmn[OUT];

    int b = blockIdx.x;
    int t = threadIdx.x;
    int w = t >> 5;
    int lane = t & 31;

    for (int i = t; i < H; i += 128) spk[i] = g_spk[b * H + i];

    // layer-1 partial fold (max/min exactly associative)
    float fmx = -CUDART_INF_F, fmn = CUDART_INF_F;
    for (int k = t; k < NQ; k += 128) {
        fmx = fmaxf(fmx, g_pmax[k * B + b]);
        fmn = fminf(fmn, g_pmin[k * B + b]);
    }
#pragma unroll
    for (int off = 16; off > 0; off >>= 1) {
        fmx = fmaxf(fmx, __shfl_xor_sync(0xffffffffu, fmx, off));
        fmn = fminf(fmn, __shfl_xor_sync(0xffffffffu, fmn, off));
    }
    if (lane == 0) { s_fmx[w] = fmx; s_fmn[w] = fmn; }

    __syncthreads();   // spk ready

    if (lane < OUT) {
        const float* w2 = W2 + lane * H;
        float q = 0.0f, px = -CUDART_INF_F, pn = CUDART_INF_F;
        float tr = 0.0f;
        if (w < 3) {
            float pa, pb, pc;
#pragma unroll 1
            for (int lc = 0; lc < 8; ++lc) {
                float s = chunk16_l2(spk, w2, (w * 8 + lc) * 16, q, px, pn);
                if (lc & 1) { s = pa + s;
                    if (lc & 2) { s = pb + s;
                        if (lc & 4) { tr = pc + s; }
                        else pc = s;
                    } else pb = s;
                } else pa = s;
            }
        } else {
            tr = chunk16_l2(spk, w2, 384, q, px, pn);  // leftover chunk 24
        }
        s_t[w][lane]  = tr;
        s_px[w][lane] = px;
        s_pn[w][lane] = pn;
    }
    __syncthreads();

    if (t < OUT) {
        float t0 = s_t[0][t], t1 = s_t[1][t], t2 = s_t[2][t], L = s_t[3][t];
        float m0 = h2_mem0[t];
        float S = ((t0 + t1) + t2) + L;
        float fin = m0 + S;
        float o1 = t0, o2 = t0 + t1, o3 = o2 + t2;
        float mx = fmaxf(fmaxf(s_px[0][t], o1 + s_px[1][t]),
                         fmaxf(o2 + s_px[2][t], o3 + s_px[3][t]));
        float mn = fminf(fminf(s_pn[0][t], o1 + s_pn[1][t]),
                         fminf(o2 + s_pn[2][t], o3 + s_pn[3][t]));
        s_nmx[t] = m0 + mx;
        s_nmn[t] = m0 + mn;
        bool sp = fin > THRESH;
        out_h2s[b * OUT + t]   = sp ? 1.0f : 0.0f;
        out_h2mem[b * OUT + t] = sp ? 0.0f : fin * DECAY;
    }
    __syncthreads();

    if (t == 0) {
        float mx = fmaxf(fmaxf(s_fmx[0], s_fmx[1]), fmaxf(s_fmx[2], s_fmx[3]));
        float mn = fminf(fminf(s_fmn[0], s_fmn[1]), fminf(s_fmn[2], s_fmn[3]));
#pragma unroll
        for (int i = 0; i < OUT; ++i) {
            mx = fmaxf(mx, s_nmx[i]);
            mn = fminf(mn, s_nmn[i]);
        }
        out_smax[b] = mx;
        out_smin[b] = mn;
    }
}

// ---------------------------------------------------------------------------
// Launch. Output layout = flat concat of reference return tuple:
//   h2_spiked [B*OUT] | step_max [B] | step_min [B] | h1_mem [B*H] | h2_mem [B*OUT]
// ---------------------------------------------------------------------------
extern "C" void kernel_launch(void* const* d_in, const int* in_sizes, int n_in,
                              void* d_out, int out_size) {
    const float* input_vec = (const float*)d_in[0];
    const float* W1        = (const float*)d_in[1];
    const float* W2        = (const float*)d_in[2];
    const float* h1_mem0   = (const float*)d_in[3];
    const float* h2_mem0   = (const float*)d_in[4];

    float* out = (float*)d_out;
    float* out_h2s   = out;                            // B*OUT
    float* out_smax  = out + B * OUT;                  // B
    float* out_smin  = out + B * OUT + B;              // B
    float* out_h1mem = out + B * OUT + 2 * B;          // B*H
    float* out_h2mem = out + B * OUT + 2 * B + B * H;  // B*OUT

    k_pack<<<B, 800>>>(input_vec);
    k_layer1<<<dim3(NQ, B / BG), BG * ES>>>(W1, h1_mem0, out_h1mem);
    k_layer2<<<B, 128>>>(W2, h2_mem0, out_h2s, out_smax, out_smin, out_h2mem);
}